// round 12
// baseline (speedup 1.0000x reference)
#include <cuda_runtime.h>
#include <cstdint>

#define D_MODEL 1024
#define NB 4
#define NCTA 128
#define NTHREADS 384          // warps 0-7: compute (1 row each); 8-11: stagers
#define TP1_MAX 2049
#define BOS 0

typedef unsigned long long u64;

// Tagged hidden state: one 64-bit word per element = {tag:32 | value_bits:32}.
// Producer of h_t stores tag = t+1 in the SAME 8-byte scalar relaxed-atomic
// store as the value (single-copy atomic -> no tearing; proven R8).
// Double-buffered by t&1; 4-chain interleave bounds skew (proven R8).
__device__ u64 g_hbuf2[2][NB][D_MODEL];

__global__ void rnn_init_kernel() {
    int i = blockIdx.x * blockDim.x + threadIdx.x;
    if (i < 2 * NB * D_MODEL)
        reinterpret_cast<u64*>(g_hbuf2)[i] = 0ull;   // tag 0 == h_{-1}
}

__device__ __forceinline__ u64 ld_relaxed_u64(const u64* p) {
    u64 v;
    asm volatile("ld.relaxed.gpu.global.u64 %0, [%1];" : "=l"(v) : "l"(p) : "memory");
    return v;
}
__device__ __forceinline__ void st_relaxed_u64(u64* p, u64 v) {
    asm volatile("st.relaxed.gpu.global.u64 [%0], %1;" :: "l"(p), "l"(v) : "memory");
}

// Persistent kernel, R8 skeleton with WARP SPECIALIZATION:
//   warps 0-7  (compute): matvec(W row in regs, h from smem) + shfl reduce +
//                         tagged publish of h_t. NO global loads on their
//                         pre-barrier critical path.
//   warps 8-11 (stagers): load next unit's input (8 tagged u64/lane, data
//                         published 3 iterations earlier), absorb L2 latency
//                         + tag check + unpack into hsm[q^1], then barrier.
// Units (t, b): 4 interleaved batch chains, dependency distance 4 units,
// ONE __syncthreads per unit.
__global__ void __launch_bounds__(NTHREADS, 1)
rnn_scan_kernel(const int*   __restrict__ ids,
                const float* __restrict__ emb,
                const float* __restrict__ W,
                float*       __restrict__ out,
                int Tp1)
{
    __shared__ unsigned short ids_sm[NB * TP1_MAX];  // tokens incl. BOS (vocab<65536)
    __shared__ float4 hsm[2][D_MODEL / 4];           // staged h (one unit), dbl-buf

    const int tid  = threadIdx.x;
    const int lane = tid & 31;
    const int w    = tid >> 5;
    const bool is_compute = (w < 8);
    const int row  = blockIdx.x * 8 + w;             // valid for compute warps

    // ---- compute warps: W row -> registers (32 floats/lane) ----
    float4 wr[8];
    if (is_compute) {
        const float4* __restrict__ Wv = reinterpret_cast<const float4*>(W);
#pragma unroll
        for (int k = 0; k < 8; ++k) wr[k] = Wv[(size_t)row * 256 + lane + 32 * k];
    }

    // ---- stage token ids with BOS prepended ----
    const int T = Tp1 - 1;
    for (int i = tid; i < NB * Tp1; i += NTHREADS) {
        int b = i / Tp1;
        int t = i - b * Tp1;
        ids_sm[i] = (unsigned short)((t == 0) ? BOS : ids[b * T + (t - 1)]);
    }
    if (tid < 256) hsm[0][tid] = make_float4(0.f, 0.f, 0.f, 0.f);  // h_{-1}=0
    __syncthreads();

    // ---- compute lane0: embedding prefetch, statically indexed per chain ----
    float e_pref[NB];
    if (is_compute && lane == 0) {
#pragma unroll
        for (int b = 0; b < NB; ++b)
            e_pref[b] = emb[(size_t)ids_sm[b * Tp1] * D_MODEL + row];
    }

    // stager identity: 128 stager threads, each owns 8 consecutive h elements
    const int sj = tid - 256;                        // 0..127 for stagers
    float2* const hw[2] = { reinterpret_cast<float2*>(hsm[0]),
                            reinterpret_cast<float2*>(hsm[1]) };

    for (int t = 0; t < Tp1; ++t) {
#pragma unroll
        for (int b = 0; b < NB; ++b) {
            const int q = b & 1;                     // (4t+b)&1, static

            if (is_compute) {
                // ---- C. matvec: full row per warp, 4 accumulators ----
                const float4* __restrict__ h4 = hsm[q];
                float a0 = 0.f, a1 = 0.f, a2 = 0.f, a3 = 0.f;
#pragma unroll
                for (int kk = 0; kk < 8; kk += 4) {
                    float4 h0 = h4[lane + 32 * (kk + 0)];
                    float4 h1 = h4[lane + 32 * (kk + 1)];
                    float4 h2 = h4[lane + 32 * (kk + 2)];
                    float4 h3 = h4[lane + 32 * (kk + 3)];
                    a0 += wr[kk + 0].x * h0.x; a0 += wr[kk + 0].y * h0.y;
                    a0 += wr[kk + 0].z * h0.z; a0 += wr[kk + 0].w * h0.w;
                    a1 += wr[kk + 1].x * h1.x; a1 += wr[kk + 1].y * h1.y;
                    a1 += wr[kk + 1].z * h1.z; a1 += wr[kk + 1].w * h1.w;
                    a2 += wr[kk + 2].x * h2.x; a2 += wr[kk + 2].y * h2.y;
                    a2 += wr[kk + 2].z * h2.z; a2 += wr[kk + 2].w * h2.w;
                    a3 += wr[kk + 3].x * h3.x; a3 += wr[kk + 3].y * h3.y;
                    a3 += wr[kk + 3].z * h3.z; a3 += wr[kk + 3].w * h3.w;
                }
                float a = (a0 + a1) + (a2 + a3);
#pragma unroll
                for (int off = 16; off > 0; off >>= 1)
                    a += __shfl_xor_sync(0xffffffffu, a, off);

                // ---- D. epilogue: h_t = dot + emb; tagged publish ----
                if (lane == 0) {
                    float v = a + e_pref[b];
                    st_relaxed_u64(&g_hbuf2[t & 1][b][row],
                                   ((u64)(unsigned)(t + 1) << 32) |
                                   (u64)__float_as_uint(v));
                    out[((size_t)b * Tp1 + t) * D_MODEL + row] = v;
                    if (t + 1 < Tp1)  // for (t+1, b), consumed 4 units later
                        e_pref[b] = emb[(size_t)ids_sm[b * Tp1 + t + 1] * D_MODEL + row];
                }
            } else {
                // ---- B+E (stagers): fetch + check + unpack unit u+1 input ----
                // next unit: (t, b+1) if b<3 else (t+1, 0); its input h_{tn-1}
                // was published 3 iterations ago -> no spin in steady state.
                const int  bn = (b < 3) ? b + 1 : 0;
                const int  tn = (b < 3) ? t : t + 1;
                if (tn < Tp1) {
                    const int slot = (tn + 1) & 1;   // h_{tn-1} lives here
                    const u64* sp = &g_hbuf2[slot][bn][8 * sj];
                    const unsigned exp = (unsigned)tn;
                    u64 v0 = ld_relaxed_u64(sp + 0), v1 = ld_relaxed_u64(sp + 1);
                    u64 v2 = ld_relaxed_u64(sp + 2), v3 = ld_relaxed_u64(sp + 3);
                    u64 v4 = ld_relaxed_u64(sp + 4), v5 = ld_relaxed_u64(sp + 5);
                    u64 v6 = ld_relaxed_u64(sp + 6), v7 = ld_relaxed_u64(sp + 7);
                    while ((unsigned)(v0 >> 32) != exp || (unsigned)(v1 >> 32) != exp ||
                           (unsigned)(v2 >> 32) != exp || (unsigned)(v3 >> 32) != exp ||
                           (unsigned)(v4 >> 32) != exp || (unsigned)(v5 >> 32) != exp ||
                           (unsigned)(v6 >> 32) != exp || (unsigned)(v7 >> 32) != exp) {
                        v0 = ld_relaxed_u64(sp + 0); v1 = ld_relaxed_u64(sp + 1);
                        v2 = ld_relaxed_u64(sp + 2); v3 = ld_relaxed_u64(sp + 3);
                        v4 = ld_relaxed_u64(sp + 4); v5 = ld_relaxed_u64(sp + 5);
                        v6 = ld_relaxed_u64(sp + 6); v7 = ld_relaxed_u64(sp + 7);
                    }
                    float2* dst = hw[q ^ 1] + 4 * sj;
                    dst[0] = make_float2(__uint_as_float((unsigned)v0),
                                         __uint_as_float((unsigned)v1));
                    dst[1] = make_float2(__uint_as_float((unsigned)v2),
                                         __uint_as_float((unsigned)v3));
                    dst[2] = make_float2(__uint_as_float((unsigned)v4),
                                         __uint_as_float((unsigned)v5));
                    dst[3] = make_float2(__uint_as_float((unsigned)v6),
                                         __uint_as_float((unsigned)v7));
                }
            }

            // ---- F. single barrier per unit ----
            __syncthreads();
        }
    }
}

extern "C" void kernel_launch(void* const* d_in, const int* in_sizes, int n_in,
                              void* d_out, int out_size) {
    const int*   ids = (const int*)d_in[0];
    const float* emb = (const float*)d_in[1];
    const float* W   = (const float*)d_in[2];
    float* out = (float*)d_out;

    int Tp1 = out_size / (NB * D_MODEL);   // 2049 for the reference shapes
    if (Tp1 > TP1_MAX) Tp1 = TP1_MAX;

    rnn_init_kernel<<<32, 256>>>();
    rnn_scan_kernel<<<NCTA, NTHREADS>>>(ids, emb, W, out, Tp1);
}

// round 13
// speedup vs baseline: 1.2691x; 1.2691x over previous
#include <cuda_runtime.h>
#include <cstdint>

#define D_MODEL 1024
#define NB 4
#define NCTA 64               // halved participant population (was 128)
#define NTHREADS 512          // 16 warps, one full row per warp
#define ROWS_PER_CTA 16
#define TP1_MAX 2049
#define BOS 0

typedef unsigned long long u64;

// Tagged hidden state: one 64-bit word per element = {tag:32 | value_bits:32}.
// Producer of h_t stores tag = t+1 in the SAME 8-byte scalar relaxed-atomic
// store as the value (single-copy atomic -> no tearing; proven R8).
// Double-buffered by t&1; 4-chain interleave bounds skew (proven R8).
__device__ u64 g_hbuf2[2][NB][D_MODEL];

__global__ void rnn_init_kernel() {
    int i = blockIdx.x * blockDim.x + threadIdx.x;
    if (i < 2 * NB * D_MODEL)
        reinterpret_cast<u64*>(g_hbuf2)[i] = 0ull;   // tag 0 == h_{-1}
}

__device__ __forceinline__ u64 ld_relaxed_u64(const u64* p) {
    u64 v;
    asm volatile("ld.relaxed.gpu.global.u64 %0, [%1];" : "=l"(v) : "l"(p) : "memory");
    return v;
}
__device__ __forceinline__ void st_relaxed_u64(u64* p, u64 v) {
    asm volatile("st.relaxed.gpu.global.u64 [%0], %1;" :: "l"(p), "l"(v) : "memory");
}

// Persistent kernel: R8 skeleton exactly, but 64 CTAs x 16 rows.
// Per-warp work is identical to R8 (one full row, 32 W floats/lane, 4-acc
// matvec + 5-shfl reduce). Units (t, b): 4 interleaved batch chains,
// dependency distance 4 units, ONE __syncthreads per unit, tagged-u64
// publish/stage protocol. The only change vs R8 is the participant count:
// tests whether the ~1030 cyc/unit pace is E[max jitter over NCTA CTAs].
__global__ void __launch_bounds__(NTHREADS, 1)
rnn_scan_kernel(const int*   __restrict__ ids,
                const float* __restrict__ emb,
                const float* __restrict__ W,
                float*       __restrict__ out,
                int Tp1)
{
    __shared__ unsigned short ids_sm[NB * TP1_MAX];  // tokens incl. BOS (vocab<65536)
    __shared__ float4 hsm[2][D_MODEL / 4];           // staged h (one unit), dbl-buf

    const int tid  = threadIdx.x;
    const int lane = tid & 31;
    const int w    = tid >> 5;
    const int row  = blockIdx.x * ROWS_PER_CTA + w;  // this warp's W row

    // ---- W row -> registers: 32 floats/lane (cols 4*(lane + 32k)) ----
    const float4* __restrict__ Wv = reinterpret_cast<const float4*>(W);
    float4 wr[8];
#pragma unroll
    for (int k = 0; k < 8; ++k) wr[k] = Wv[(size_t)row * 256 + lane + 32 * k];

    // ---- stage token ids with BOS prepended ----
    const int T = Tp1 - 1;
    for (int i = tid; i < NB * Tp1; i += NTHREADS) {
        int b = i / Tp1;
        int t = i - b * Tp1;
        ids_sm[i] = (unsigned short)((t == 0) ? BOS : ids[b * T + (t - 1)]);
    }
    if (tid < 256) hsm[0][tid] = make_float4(0.f, 0.f, 0.f, 0.f);  // h_{-1}=0
    __syncthreads();

    // ---- embedding prefetch (lane0): statically-indexed per chain ----
    float e_pref[NB];
    if (lane == 0) {
#pragma unroll
        for (int b = 0; b < NB; ++b)
            e_pref[b] = emb[(size_t)ids_sm[b * Tp1] * D_MODEL + row];
    }

    float2* const hw[2] = { reinterpret_cast<float2*>(hsm[0]),
                            reinterpret_cast<float2*>(hsm[1]) };

    for (int t = 0; t < Tp1; ++t) {
#pragma unroll
        for (int b = 0; b < NB; ++b) {
            const int q = b & 1;                     // (4t+b)&1, static

            // ---- B. issue tagged stage loads for unit u+1's input ----
            // next unit: (t, b+1) if b<3 else (t+1, 0); its input h_{tn-1}(bn)
            // was published 3 iterations earlier (unit u-3's epilogue).
            const int  bn = (b < 3) ? b + 1 : 0;
            const int  tn = (b < 3) ? t : t + 1;
            const bool have_next = (tn < Tp1);
            const u64* sp = nullptr;
            u64 s0v, s1v;
            const unsigned exp = (unsigned)tn;       // tag of h_{tn-1}
            if (have_next) {
                const int slot = (tn + 1) & 1;       // h_{tn-1} lives here
                sp  = &g_hbuf2[slot][bn][2 * tid];
                s0v = ld_relaxed_u64(sp + 0);
                s1v = ld_relaxed_u64(sp + 1);
            }

            // ---- C. matvec: full row per warp, 4 accumulators ----
            const float4* __restrict__ h4 = hsm[q];
            float a0 = 0.f, a1 = 0.f, a2 = 0.f, a3 = 0.f;
#pragma unroll
            for (int kk = 0; kk < 8; kk += 4) {
                float4 h0 = h4[lane + 32 * (kk + 0)];
                float4 h1 = h4[lane + 32 * (kk + 1)];
                float4 h2 = h4[lane + 32 * (kk + 2)];
                float4 h3 = h4[lane + 32 * (kk + 3)];
                a0 += wr[kk + 0].x * h0.x; a0 += wr[kk + 0].y * h0.y;
                a0 += wr[kk + 0].z * h0.z; a0 += wr[kk + 0].w * h0.w;
                a1 += wr[kk + 1].x * h1.x; a1 += wr[kk + 1].y * h1.y;
                a1 += wr[kk + 1].z * h1.z; a1 += wr[kk + 1].w * h1.w;
                a2 += wr[kk + 2].x * h2.x; a2 += wr[kk + 2].y * h2.y;
                a2 += wr[kk + 2].z * h2.z; a2 += wr[kk + 2].w * h2.w;
                a3 += wr[kk + 3].x * h3.x; a3 += wr[kk + 3].y * h3.y;
                a3 += wr[kk + 3].z * h3.z; a3 += wr[kk + 3].w * h3.w;
            }
            float a = (a0 + a1) + (a2 + a3);
#pragma unroll
            for (int off = 16; off > 0; off >>= 1)
                a += __shfl_xor_sync(0xffffffffu, a, off);

            // ---- D. epilogue: h_t = dot + emb; tagged publish ----
            if (lane == 0) {
                float v = a + e_pref[b];
                st_relaxed_u64(&g_hbuf2[t & 1][b][row],
                               ((u64)(unsigned)(t + 1) << 32) |
                               (u64)__float_as_uint(v));
                out[((size_t)b * Tp1 + t) * D_MODEL + row] = v;
                if (t + 1 < Tp1)   // prefetch for (t+1, b), consumed 4 units later
                    e_pref[b] = emb[(size_t)ids_sm[b * Tp1 + t + 1] * D_MODEL + row];
            }

            // ---- E. tag check (the ONLY wait) + publish stage to smem ----
            if (have_next) {
                while ((unsigned)(s0v >> 32) != exp ||
                       (unsigned)(s1v >> 32) != exp) {
                    s0v = ld_relaxed_u64(sp + 0);
                    s1v = ld_relaxed_u64(sp + 1);
                }
                hw[q ^ 1][tid] = make_float2(__uint_as_float((unsigned)s0v),
                                             __uint_as_float((unsigned)s1v));
            }

            // ---- F. single barrier per unit ----
            __syncthreads();
        }
    }
}

extern "C" void kernel_launch(void* const* d_in, const int* in_sizes, int n_in,
                              void* d_out, int out_size) {
    const int*   ids = (const int*)d_in[0];
    const float* emb = (const float*)d_in[1];
    const float* W   = (const float*)d_in[2];
    float* out = (float*)d_out;

    int Tp1 = out_size / (NB * D_MODEL);   // 2049 for the reference shapes
    if (Tp1 > TP1_MAX) Tp1 = TP1_MAX;

    rnn_init_kernel<<<32, 256>>>();
    rnn_scan_kernel<<<NCTA, NTHREADS>>>(ids, emb, W, out, Tp1);
}

// round 15
// speedup vs baseline: 1.6287x; 1.2833x over previous
#include <cuda_runtime.h>
#include <cstdint>

#define D_MODEL 1024
#define NB 4
#define NCTA 128
#define NTHREADS 256          // 8 warps, one row per warp
#define TP1_MAX 2049
#define BOS 0

typedef unsigned long long u64;

// Tagged hidden state: one 64-bit word per element = {tag:32 | value_bits:32}.
// Producer of h_t stores tag = t+1 in the SAME 8-byte scalar relaxed-atomic
// store as the value (single-copy atomic -> no tearing; proven R8).
// Double-buffered by t&1; 4-chain interleave bounds skew (proven R8).
__device__ u64 g_hbuf2[2][NB][D_MODEL];

__global__ void rnn_init_kernel() {
    int i = blockIdx.x * blockDim.x + threadIdx.x;
    if (i < 2 * NB * D_MODEL)
        reinterpret_cast<u64*>(g_hbuf2)[i] = 0ull;   // tag 0 == h_{-1}
}

__device__ __forceinline__ u64 ld_relaxed_u64(const u64* p) {
    u64 v;
    asm volatile("ld.relaxed.gpu.global.u64 %0, [%1];" : "=l"(v) : "l"(p) : "memory");
    return v;
}
__device__ __forceinline__ void st_relaxed_u64(u64* p, u64 v) {
    asm volatile("st.relaxed.gpu.global.u64 [%0], %1;" :: "l"(p), "l"(v) : "memory");
}

// Persistent kernel: R8 skeleton (128 CTAs x 8 rows, one full row per warp,
// 4-chain interleave, tagged-u64 protocol, ONE __syncthreads per unit) with a
// DEPTH-2 STAGING PIPELINE:
//   iteration u: issue loads for unit u+2's input (4 u64/thread -> full 1024
//   coverage at 256 threads; R14's bug was 2/thread = half coverage);
//   CHECK the registers staged during iteration u-1 (for unit u+1) -- a full
//   iteration old, so the tag compare is pure ALU, no scoreboard wait;
//   unpack to hsm[(u+1)&1]; barrier.
__global__ void __launch_bounds__(NTHREADS, 1)
rnn_scan_kernel(const int*   __restrict__ ids,
                const float* __restrict__ emb,
                const float* __restrict__ W,
                float*       __restrict__ out,
                int Tp1)
{
    __shared__ unsigned short ids_sm[NB * TP1_MAX];  // tokens incl. BOS
    __shared__ float4 hsm[2][D_MODEL / 4];           // staged h (one unit), dbl-buf

    const int tid  = threadIdx.x;
    const int lane = tid & 31;
    const int w    = tid >> 5;
    const int row  = blockIdx.x * 8 + w;             // this warp's W row

    // ---- W row -> registers: 32 floats/lane (cols 4*(lane + 32k)) ----
    const float4* __restrict__ Wv = reinterpret_cast<const float4*>(W);
    float4 wr[8];
#pragma unroll
    for (int k = 0; k < 8; ++k) wr[k] = Wv[(size_t)row * 256 + lane + 32 * k];

    // ---- stage token ids with BOS prepended ----
    const int T = Tp1 - 1;
    for (int i = tid; i < NB * Tp1; i += NTHREADS) {
        int b = i / Tp1;
        int t = i - b * Tp1;
        ids_sm[i] = (unsigned short)((t == 0) ? BOS : ids[b * T + (t - 1)]);
    }
    hsm[0][tid] = make_float4(0.f, 0.f, 0.f, 0.f);   // input of unit 0 (h_{-1}=0)
    __syncthreads();

    // ---- embedding prefetch (lane0): statically-indexed per chain ----
    float e_pref[NB];
    if (lane == 0) {
#pragma unroll
        for (int b = 0; b < NB; ++b)
            e_pref[b] = emb[(size_t)ids_sm[b * Tp1] * D_MODEL + row];
    }

    // ---- preload stage regs for unit 1 (input h_{-1}(1): slot 1, tag 0) ----
    u64 s0v, s1v, s2v, s3v;
    {
        const u64* p1 = &g_hbuf2[1][1][4 * tid];
        s0v = ld_relaxed_u64(p1 + 0);
        s1v = ld_relaxed_u64(p1 + 1);
        s2v = ld_relaxed_u64(p1 + 2);
        s3v = ld_relaxed_u64(p1 + 3);
    }

    for (int t = 0; t < Tp1; ++t) {
#pragma unroll
        for (int b = 0; b < NB; ++b) {
            const int q = b & 1;                     // (4t+b)&1, static

            // ---- B. issue tagged loads for unit u+2's input (depth-2) ----
            // u+2: (t, b+2) for b<2, else (t+1, b-2). Its input h_{t2-1}(b2)
            // was published at D of iteration u-2.
            const int  b2 = (b + 2) & 3;
            const int  t2 = (b < 2) ? t : t + 1;
            u64 n0v = 0, n1v = 0, n2v = 0, n3v = 0;
            if (t2 < Tp1) {
                const u64* np = &g_hbuf2[(t2 + 1) & 1][b2][4 * tid];
                n0v = ld_relaxed_u64(np + 0);
                n1v = ld_relaxed_u64(np + 1);
                n2v = ld_relaxed_u64(np + 2);
                n3v = ld_relaxed_u64(np + 3);
            }

            // ---- C. matvec: full row per warp, 4 accumulators ----
            const float4* __restrict__ h4 = hsm[q];
            float a0 = 0.f, a1 = 0.f, a2 = 0.f, a3 = 0.f;
#pragma unroll
            for (int kk = 0; kk < 8; kk += 4) {
                float4 h0 = h4[lane + 32 * (kk + 0)];
                float4 h1 = h4[lane + 32 * (kk + 1)];
                float4 h2 = h4[lane + 32 * (kk + 2)];
                float4 h3 = h4[lane + 32 * (kk + 3)];
                a0 += wr[kk + 0].x * h0.x; a0 += wr[kk + 0].y * h0.y;
                a0 += wr[kk + 0].z * h0.z; a0 += wr[kk + 0].w * h0.w;
                a1 += wr[kk + 1].x * h1.x; a1 += wr[kk + 1].y * h1.y;
                a1 += wr[kk + 1].z * h1.z; a1 += wr[kk + 1].w * h1.w;
                a2 += wr[kk + 2].x * h2.x; a2 += wr[kk + 2].y * h2.y;
                a2 += wr[kk + 2].z * h2.z; a2 += wr[kk + 2].w * h2.w;
                a3 += wr[kk + 3].x * h3.x; a3 += wr[kk + 3].y * h3.y;
                a3 += wr[kk + 3].z * h3.z; a3 += wr[kk + 3].w * h3.w;
            }
            float a = (a0 + a1) + (a2 + a3);
#pragma unroll
            for (int off = 16; off > 0; off >>= 1)
                a += __shfl_xor_sync(0xffffffffu, a, off);

            // ---- D. epilogue: h_t = dot + emb; tagged publish ----
            if (lane == 0) {
                float v = a + e_pref[b];
                st_relaxed_u64(&g_hbuf2[t & 1][b][row],
                               ((u64)(unsigned)(t + 1) << 32) |
                               (u64)__float_as_uint(v));
                out[((size_t)b * Tp1 + t) * D_MODEL + row] = v;
                if (t + 1 < Tp1)   // prefetch for (t+1, b), consumed 4 units later
                    e_pref[b] = emb[(size_t)ids_sm[b * Tp1 + t + 1] * D_MODEL + row];
            }

            // ---- E. check LAST iteration's staged regs (unit u+1) ----
            const int  bn = (b < 3) ? b + 1 : 0;
            const int  tn = (b < 3) ? t : t + 1;
            if (tn < Tp1) {
                const unsigned exp = (unsigned)tn;   // tag of h_{tn-1}
                if ((unsigned)(s0v >> 32) != exp || (unsigned)(s1v >> 32) != exp ||
                    (unsigned)(s2v >> 32) != exp || (unsigned)(s3v >> 32) != exp) {
                    const u64* sp = &g_hbuf2[(tn + 1) & 1][bn][4 * tid];
                    do {
                        s0v = ld_relaxed_u64(sp + 0);
                        s1v = ld_relaxed_u64(sp + 1);
                        s2v = ld_relaxed_u64(sp + 2);
                        s3v = ld_relaxed_u64(sp + 3);
                    } while ((unsigned)(s0v >> 32) != exp ||
                             (unsigned)(s1v >> 32) != exp ||
                             (unsigned)(s2v >> 32) != exp ||
                             (unsigned)(s3v >> 32) != exp);
                }
                hsm[q ^ 1][tid] = make_float4(__uint_as_float((unsigned)s0v),
                                              __uint_as_float((unsigned)s1v),
                                              __uint_as_float((unsigned)s2v),
                                              __uint_as_float((unsigned)s3v));
            }

            // rotate: u+2's loads become next iteration's u+1 check
            s0v = n0v; s1v = n1v; s2v = n2v; s3v = n3v;

            // ---- F. single barrier per unit ----
            __syncthreads();
        }
    }
}

extern "C" void kernel_launch(void* const* d_in, const int* in_sizes, int n_in,
                              void* d_out, int out_size) {
    const int*   ids = (const int*)d_in[0];
    const float* emb = (const float*)d_in[1];
    const float* W   = (const float*)d_in[2];
    float* out = (float*)d_out;

    int Tp1 = out_size / (NB * D_MODEL);   // 2049 for the reference shapes
    if (Tp1 > TP1_MAX) Tp1 = TP1_MAX;

    rnn_init_kernel<<<32, 256>>>();
    rnn_scan_kernel<<<NCTA, NTHREADS>>>(ids, emb, W, out, Tp1);
}